// round 14
// baseline (speedup 1.0000x reference)
#include <cuda_runtime.h>

#define N_NODE 4096
#define KNN 32
#define KSEL 33            /* top-33 incl. self (self contributes zero) */
#define HIDDEN 128
#define RMS_EPS 1e-5f
#define TABLE_N 2048
#define NQ 8
#define CAP 320
#define NBUCK 256

__device__ float g_table[TABLE_N];
__device__ float4 g_pos4[N_NODE];

typedef unsigned long long u64;

static __device__ __forceinline__ u64 ullmin2(u64 a, u64 b) { return (b < a) ? b : a; }

// ---------------------------------------------------------------------------
// Kernel 1: table of s(u), u = r/(1+r); 2 samples per warp (256 table blocks
// for more parallelism); prep (pos -> float4) fused as extra blocks.
// ---------------------------------------------------------------------------
__global__ void __launch_bounds__(128, 8)
table_prep_kernel(const float* __restrict__ pos,
                  const float* __restrict__ t,
                  const float* __restrict__ W1,
                  const float* __restrict__ b1,
                  const float* __restrict__ g1,
                  const float* __restrict__ W2,
                  const float* __restrict__ b2,
                  const float* __restrict__ g2,
                  const float* __restrict__ W3,
                  const float* __restrict__ b3) {
    const int tid = threadIdx.x;

    if (blockIdx.x >= TABLE_N / 8) {
        int j = (blockIdx.x - TABLE_N / 8) * 128 + tid;
        if (j < N_NODE)
            g_pos4[j] = make_float4(pos[3 * j], pos[3 * j + 1], pos[3 * j + 2], 0.0f);
        return;
    }

    __shared__ float h1s[4][HIDDEN * 2];
    __shared__ float sa[128], sc[128], sg1[128], sg2[128], sW3[128];
    __shared__ float sABC[3];
    __shared__ float sred[12];

    const int w = tid >> 5, lane = tid & 31;

    {
        const int k = tid;
        float t0 = t[0];
        float a = W1[2 * k];
        float c = fmaf(t0, W1[2 * k + 1], b1[k]);
        sa[k] = a; sc[k] = c;
        sg1[k] = g1[k]; sg2[k] = g2[k]; sW3[k] = W3[k];
        float pa = a * a, pb = a * c, pc = c * c;
        #pragma unroll
        for (int off = 16; off > 0; off >>= 1) {
            pa += __shfl_down_sync(0xffffffffu, pa, off);
            pb += __shfl_down_sync(0xffffffffu, pb, off);
            pc += __shfl_down_sync(0xffffffffu, pc, off);
        }
        if (lane == 0) { sred[w] = pa; sred[4 + w] = pb; sred[8 + w] = pc; }
    }
    __syncthreads();
    if (tid == 0) {
        const float inv = 1.0f / HIDDEN;
        sABC[0] = (sred[0] + sred[1] + sred[2] + sred[3]) * inv;
        sABC[1] = (sred[4] + sred[5] + sred[6] + sred[7]) * inv;
        sABC[2] = (sred[8] + sred[9] + sred[10] + sred[11]) * inv;
    }
    __syncthreads();

    const float A = sABC[0], Bc = sABC[1], C = sABC[2];
    const int s0 = blockIdx.x * 8 + w * 2;
    float* h1b = h1s[w];

    #pragma unroll
    for (int q = 0; q < 2; q++) {
        float u = (float)(s0 + q) * (1.0f / (float)(TABLE_N - 1));
        float om = 1.0f - u;
        float r = (om > 1e-8f) ? (u / om) : 1e9f;
        float den = fmaf(fmaf(r, A, 2.0f * Bc), r, C) + RMS_EPS;
        float scl = rsqrtf(den);
        #pragma unroll
        for (int p = 0; p < 4; p++) {
            int k = lane + 32 * p;
            float x = fmaf(r, sa[k], sc[k]);
            float v = x * scl * sg1[k];
            float h = v * (1.0f / (1.0f + __expf(-v)));
            h1b[k * 2 + q] = h;
        }
    }
    __syncwarp();

    float acc[4][2];
    #pragma unroll
    for (int p = 0; p < 4; p++)
        #pragma unroll
        for (int q = 0; q < 2; q++) acc[p][q] = 0.0f;

    const float4* wr0 = (const float4*)(W2 + (lane)      * HIDDEN);
    const float4* wr1 = (const float4*)(W2 + (lane + 32) * HIDDEN);
    const float4* wr2 = (const float4*)(W2 + (lane + 64) * HIDDEN);
    const float4* wr3 = (const float4*)(W2 + (lane + 96) * HIDDEN);
    #pragma unroll 4
    for (int kk = 0; kk < 32; kk++) {
        float4 w0 = __ldg(wr0 + kk), w1 = __ldg(wr1 + kk);
        float4 w2 = __ldg(wr2 + kk), w3 = __ldg(wr3 + kk);
        float w0a[4] = {w0.x, w0.y, w0.z, w0.w};
        float w1a[4] = {w1.x, w1.y, w1.z, w1.w};
        float w2a[4] = {w2.x, w2.y, w2.z, w2.w};
        float w3a[4] = {w3.x, w3.y, w3.z, w3.w};
        #pragma unroll
        for (int kq = 0; kq < 4; kq++) {
            float2 hv = *(const float2*)(h1b + (4 * kk + kq) * 2);
            float hva[2] = {hv.x, hv.y};
            #pragma unroll
            for (int q = 0; q < 2; q++) {
                acc[0][q] = fmaf(w0a[kq], hva[q], acc[0][q]);
                acc[1][q] = fmaf(w1a[kq], hva[q], acc[1][q]);
                acc[2][q] = fmaf(w2a[kq], hva[q], acc[2][q]);
                acc[3][q] = fmaf(w3a[kq], hva[q], acc[3][q]);
            }
        }
    }

    #pragma unroll
    for (int p = 0; p < 4; p++) {
        float bb = b2[lane + 32 * p];
        #pragma unroll
        for (int q = 0; q < 2; q++) acc[p][q] += bb;
    }

    float scl2[2];
    #pragma unroll
    for (int q = 0; q < 2; q++) {
        float ss = 0.0f;
        #pragma unroll
        for (int p = 0; p < 4; p++) ss = fmaf(acc[p][q], acc[p][q], ss);
        #pragma unroll
        for (int off = 16; off > 0; off >>= 1)
            ss += __shfl_xor_sync(0xffffffffu, ss, off);
        scl2[q] = rsqrtf(ss * (1.0f / HIDDEN) + RMS_EPS);
    }

    float dot[2] = {0.0f, 0.0f};
    #pragma unroll
    for (int p = 0; p < 4; p++) {
        int m = lane + 32 * p;
        float g = sg2[m], w3v = sW3[m];
        #pragma unroll
        for (int q = 0; q < 2; q++) {
            float v = acc[p][q] * scl2[q] * g;
            float h = v * (1.0f / (1.0f + __expf(-v)));
            dot[q] = fmaf(w3v, h, dot[q]);
        }
    }
    #pragma unroll
    for (int q = 0; q < 2; q++) {
        #pragma unroll
        for (int off = 16; off > 0; off >>= 1)
            dot[q] += __shfl_xor_sync(0xffffffffu, dot[q], off);
    }
    if (lane == 0) {
        float bb3 = b3[0];
        #pragma unroll
        for (int q = 0; q < 2; q++) g_table[s0 + q] = dot[q] + bb3;
    }
}

// ---------------------------------------------------------------------------
// Kernel 2: fused kNN + eval, warp-per-query, warps independent (R11 proven
// structure). Single hot-path change vs R11: tau is scaled by 0.35 after
// sampling so the filter runs ONE pass (E[cnt]~120 in [KSEL, CAP]); the
// warp-local retry (x2.5 / x0.5) remains as the exactness guarantee.
// ---------------------------------------------------------------------------
__global__ void __launch_bounds__(256, 6)
knn_eval_kernel(float* __restrict__ out) {
    __shared__ u64 cand[NQ][CAP];          // 20 KB
    __shared__ unsigned hist[NQ][NBUCK];   // 8 KB
    __shared__ int ccnt[NQ];

    const int tid = threadIdx.x;
    const int w = tid >> 5, lane = tid & 31;
    const int i = blockIdx.x * NQ + w;
    const float4 pi = g_pos4[i];
    const unsigned FULL = 0xffffffffu;
    const float INF = __int_as_float(0x7f800000);

    u64* mycand = cand[w];
    unsigned* myhist = hist[w];

    // ---- Phase 1: tau = (8th smallest of 32 lane-minima) * 0.35 ----
    float m = INF;
    #pragma unroll
    for (int s = 0; s < 8; s++) {
        int j = lane * 128 + s * 16;
        float4 q = __ldg(&g_pos4[j]);
        float dx = pi.x - q.x, dy = pi.y - q.y, dz = pi.z - q.z;
        float d = fmaf(dx, dx, fmaf(dy, dy, dz * dz));
        m = fminf(m, d);
    }
    float tau = 0.0f;
    {
        float v = m;
        for (int r = 0; r < 8; r++) {
            float mn = v;
            #pragma unroll
            for (int off = 16; off > 0; off >>= 1)
                mn = fminf(mn, __shfl_xor_sync(FULL, mn, off));
            unsigned own = __ballot_sync(FULL, v == mn);
            if (lane == (__ffs(own) - 1)) v = INF;
            tau = mn;
        }
        tau *= 0.35f;
        if (tau <= 0.0f) tau = 1e-20f;
    }

    // ---- Phase 2: filter with warp-local exact retry ----
    int cnt;
    for (;;) {
        if (lane == 0) ccnt[w] = 0;
        __syncwarp();
        #pragma unroll 4
        for (int it = 0; it < 128; it++) {
            const int j = it * 32 + lane;
            float4 q = __ldg(&g_pos4[j]);
            float dx = pi.x - q.x, dy = pi.y - q.y, dz = pi.z - q.z;
            float d = fmaf(dx, dx, fmaf(dy, dy, dz * dz));
            if (d <= tau) {
                int p = atomicAdd(&ccnt[w], 1);
                if (p < CAP)
                    mycand[p] = ((u64)__float_as_uint(d) << 32) | (unsigned)j;
            }
        }
        __syncwarp();
        cnt = ccnt[w];
        if (cnt >= KSEL && cnt <= CAP) break;
        tau = (cnt < KSEL) ? fmaxf(tau * 2.5f, 1e-20f) : (tau * 0.5f);
    }

    // ---- Phase 3a: coarse radix (bits >> sh) ----
    const unsigned taub = __float_as_uint(tau);
    const int bl = 32 - __clz(taub | 0x10000u);   // bl >= 17 -> sh >= 9
    const int sh = bl - 8;
    const int shf = sh - 8;
    for (int b = lane; b < NBUCK; b += 32) myhist[b] = 0;
    __syncwarp();
    for (int c = lane; c < cnt; c += 32) {
        unsigned bits = (unsigned)(mycand[c] >> 32);
        atomicAdd(&myhist[bits >> sh], 1u);
    }
    __syncwarp();

    int B2, base;
    {
        const int b0 = lane * 8;
        unsigned hv[8];
        unsigned lsum = 0;
        #pragma unroll
        for (int z = 0; z < 8; z++) { hv[z] = myhist[b0 + z]; lsum += hv[z]; }
        unsigned run = lsum;
        #pragma unroll
        for (int off = 1; off < 32; off <<= 1) {
            unsigned v = __shfl_up_sync(FULL, run, off);
            if (lane >= off) run += v;
        }
        run -= lsum;
        u64 pk = 0;
        unsigned r2 = run;
        #pragma unroll
        for (int z = 0; z < 8; z++) {
            if (r2 < KSEL && r2 + hv[z] >= KSEL)
                pk = ((u64)(unsigned)(b0 + z) << 32) | r2;
            r2 += hv[z];
        }
        #pragma unroll
        for (int off = 16; off > 0; off >>= 1) {
            u64 o = __shfl_xor_sync(FULL, pk, off);
            if (o > pk) pk = o;
        }
        B2 = (int)(pk >> 32);
        base = (int)(pk & 0xffffffffu);
    }
    __syncwarp();

    // ---- Phase 3b: fine radix within bucket B2 (next 8 bits) ----
    for (int b = lane; b < NBUCK; b += 32) myhist[b] = 0;
    __syncwarp();
    for (int c = lane; c < cnt; c += 32) {
        unsigned bits = (unsigned)(mycand[c] >> 32);
        if ((int)(bits >> sh) == B2)
            atomicAdd(&myhist[(bits >> shf) & 255u], 1u);
    }
    __syncwarp();

    int B3, base3;
    {
        const int K2 = KSEL - base;
        const int b0 = lane * 8;
        unsigned hv[8];
        unsigned lsum = 0;
        #pragma unroll
        for (int z = 0; z < 8; z++) { hv[z] = myhist[b0 + z]; lsum += hv[z]; }
        unsigned run = lsum;
        #pragma unroll
        for (int off = 1; off < 32; off <<= 1) {
            unsigned v = __shfl_up_sync(FULL, run, off);
            if (lane >= off) run += v;
        }
        run -= lsum;
        u64 pk = 0;
        unsigned r2 = run;
        #pragma unroll
        for (int z = 0; z < 8; z++) {
            if ((int)r2 < K2 && (int)(r2 + hv[z]) >= K2)
                pk = ((u64)(unsigned)(b0 + z) << 32) | r2;
            r2 += hv[z];
        }
        #pragma unroll
        for (int off = 16; off > 0; off >>= 1) {
            u64 o = __shfl_xor_sync(FULL, pk, off);
            if (o > pk) pk = o;
        }
        B3 = (int)(pk >> 32);
        base3 = (int)(pk & 0xffffffffu);
    }
    __syncwarp();

    // ---- Phase 4: accumulate ----
    const float tscale = (float)(TABLE_N - 1);
    float sx = 0.0f, sy = 0.0f, sz = 0.0f;

    #define ACCUM_EDGE(_bits, _j) do {                                     \
        float4 _q = g_pos4[_j];                                            \
        float _dx = pi.x - _q.x, _dy = pi.y - _q.y, _dz = pi.z - _q.z;     \
        float _r = __uint_as_float(_bits);                                 \
        float _u = _r / (1.0f + _r);                                       \
        float _x = _u * tscale;                                            \
        int _i0 = (int)_x; if (_i0 > TABLE_N - 2) _i0 = TABLE_N - 2;       \
        float _f = _x - (float)_i0;                                        \
        float _s0 = g_table[_i0], _s1 = g_table[_i0 + 1];                  \
        float _sv = fmaf(_f, _s1 - _s0, _s0);                              \
        sx = fmaf(_dx, _sv, sx);                                           \
        sy = fmaf(_dy, _sv, sy);                                           \
        sz = fmaf(_dz, _sv, sz);                                           \
    } while (0)

    for (int c = lane; c < cnt; c += 32) {
        u64 key = mycand[c];
        unsigned bits = (unsigned)(key >> 32);
        int cb = (int)(bits >> sh);
        int fb = (int)((bits >> shf) & 255u);
        if (cb < B2 || (cb == B2 && fb < B3))
            ACCUM_EDGE(bits, (int)(key & 0xffffffffu));
    }

    const int need = KSEL - base - base3;
    for (int s = 0; s < need; s++) {
        u64 best = ~0ull;
        for (int c = lane; c < cnt; c += 32) {
            u64 k2 = mycand[c];
            unsigned bits = (unsigned)(k2 >> 32);
            if (k2 != ~0ull && (int)(bits >> sh) == B2 &&
                (int)((bits >> shf) & 255u) == B3)
                best = ullmin2(best, k2);
        }
        #pragma unroll
        for (int off = 16; off > 0; off >>= 1)
            best = ullmin2(best, __shfl_xor_sync(FULL, best, off));
        if (lane == 0) {
            unsigned bb = (unsigned)(best >> 32);
            ACCUM_EDGE(bb, (int)(best & 0xffffffffu));
        }
        for (int c = lane; c < cnt; c += 32)
            if (mycand[c] == best) mycand[c] = ~0ull;
    }
    #undef ACCUM_EDGE

    // ---- Warp reduce + write ----
    #pragma unroll
    for (int off = 16; off > 0; off >>= 1) {
        sx += __shfl_down_sync(FULL, sx, off);
        sy += __shfl_down_sync(FULL, sy, off);
        sz += __shfl_down_sync(FULL, sz, off);
    }
    if (lane == 0) {
        const float invK = 1.0f / (float)KNN;
        out[3 * i]     = pi.x + sx * invK;
        out[3 * i + 1] = pi.y + sy * invK;
        out[3 * i + 2] = pi.z + sz * invK;
    }
}

// ---------------------------------------------------------------------------
// Launch
// ---------------------------------------------------------------------------
extern "C" void kernel_launch(void* const* d_in, const int* in_sizes, int n_in,
                              void* d_out, int out_size) {
    const float* pos = (const float*)d_in[0];
    const float* t   = (const float*)d_in[1];
    const float* W1  = (const float*)d_in[2];
    const float* b1  = (const float*)d_in[3];
    const float* g1  = (const float*)d_in[4];
    const float* W2  = (const float*)d_in[5];
    const float* b2  = (const float*)d_in[6];
    const float* g2  = (const float*)d_in[7];
    const float* W3  = (const float*)d_in[8];
    const float* b3  = (const float*)d_in[9];
    float* out = (float*)d_out;

    const int table_blocks = TABLE_N / 8;             // 256
    const int prep_blocks  = (N_NODE + 127) / 128;    // 32
    table_prep_kernel<<<table_blocks + prep_blocks, 128>>>(
        pos, t, W1, b1, g1, W2, b2, g2, W3, b3);
    knn_eval_kernel<<<N_NODE / NQ, 256>>>(out);
}

// round 15
// speedup vs baseline: 1.2674x; 1.2674x over previous
#include <cuda_runtime.h>

#define N_NODE 4096
#define KNN 32
#define KSEL 33            /* top-33 incl. self (self contributes zero) */
#define HIDDEN 128
#define RMS_EPS 1e-5f
#define TABLE_N 2048
#define NQ 4
#define CAP 320
#define NBUCK 256

__device__ float g_table[TABLE_N];
__device__ float4 g_pos4[N_NODE];

typedef unsigned long long u64;

static __device__ __forceinline__ u64 ullmin2(u64 a, u64 b) { return (b < a) ? b : a; }

// ---------------------------------------------------------------------------
// Kernel 1: table of s(u), u = r/(1+r), uniform grid; 4 samples per warp
// (R11-proven config); prep (pos -> float4) fused as extra blocks.
// ---------------------------------------------------------------------------
__global__ void __launch_bounds__(128, 8)
table_prep_kernel(const float* __restrict__ pos,
                  const float* __restrict__ t,
                  const float* __restrict__ W1,
                  const float* __restrict__ b1,
                  const float* __restrict__ g1,
                  const float* __restrict__ W2,
                  const float* __restrict__ b2,
                  const float* __restrict__ g2,
                  const float* __restrict__ W3,
                  const float* __restrict__ b3) {
    const int tid = threadIdx.x;

    if (blockIdx.x >= TABLE_N / 16) {
        int j = (blockIdx.x - TABLE_N / 16) * 128 + tid;
        if (j < N_NODE)
            g_pos4[j] = make_float4(pos[3 * j], pos[3 * j + 1], pos[3 * j + 2], 0.0f);
        return;
    }

    __shared__ float h1s[4][HIDDEN * 4];
    __shared__ float sa[128], sc[128], sg1[128], sg2[128], sW3[128];
    __shared__ float sABC[3];
    __shared__ float sred[12];

    const int w = tid >> 5, lane = tid & 31;

    {
        const int k = tid;
        float t0 = t[0];
        float a = W1[2 * k];
        float c = fmaf(t0, W1[2 * k + 1], b1[k]);
        sa[k] = a; sc[k] = c;
        sg1[k] = g1[k]; sg2[k] = g2[k]; sW3[k] = W3[k];
        float pa = a * a, pb = a * c, pc = c * c;
        #pragma unroll
        for (int off = 16; off > 0; off >>= 1) {
            pa += __shfl_down_sync(0xffffffffu, pa, off);
            pb += __shfl_down_sync(0xffffffffu, pb, off);
            pc += __shfl_down_sync(0xffffffffu, pc, off);
        }
        if (lane == 0) { sred[w] = pa; sred[4 + w] = pb; sred[8 + w] = pc; }
    }
    __syncthreads();
    if (tid == 0) {
        const float inv = 1.0f / HIDDEN;
        sABC[0] = (sred[0] + sred[1] + sred[2] + sred[3]) * inv;
        sABC[1] = (sred[4] + sred[5] + sred[6] + sred[7]) * inv;
        sABC[2] = (sred[8] + sred[9] + sred[10] + sred[11]) * inv;
    }
    __syncthreads();

    const float A = sABC[0], Bc = sABC[1], C = sABC[2];
    const int s0 = blockIdx.x * 16 + w * 4;
    float* h1b = h1s[w];

    #pragma unroll
    for (int q = 0; q < 4; q++) {
        float u = (float)(s0 + q) * (1.0f / (float)(TABLE_N - 1));
        float om = 1.0f - u;
        float r = (om > 1e-8f) ? (u / om) : 1e9f;
        float den = fmaf(fmaf(r, A, 2.0f * Bc), r, C) + RMS_EPS;
        float scl = rsqrtf(den);
        #pragma unroll
        for (int p = 0; p < 4; p++) {
            int k = lane + 32 * p;
            float x = fmaf(r, sa[k], sc[k]);
            float v = x * scl * sg1[k];
            float h = v * (1.0f / (1.0f + __expf(-v)));
            h1b[k * 4 + q] = h;
        }
    }
    __syncwarp();

    float acc[4][4];
    #pragma unroll
    for (int p = 0; p < 4; p++)
        #pragma unroll
        for (int q = 0; q < 4; q++) acc[p][q] = 0.0f;

    const float4* wr0 = (const float4*)(W2 + (lane)      * HIDDEN);
    const float4* wr1 = (const float4*)(W2 + (lane + 32) * HIDDEN);
    const float4* wr2 = (const float4*)(W2 + (lane + 64) * HIDDEN);
    const float4* wr3 = (const float4*)(W2 + (lane + 96) * HIDDEN);
    #pragma unroll 2
    for (int kk = 0; kk < 32; kk++) {
        float4 w0 = __ldg(wr0 + kk), w1 = __ldg(wr1 + kk);
        float4 w2 = __ldg(wr2 + kk), w3 = __ldg(wr3 + kk);
        float w0a[4] = {w0.x, w0.y, w0.z, w0.w};
        float w1a[4] = {w1.x, w1.y, w1.z, w1.w};
        float w2a[4] = {w2.x, w2.y, w2.z, w2.w};
        float w3a[4] = {w3.x, w3.y, w3.z, w3.w};
        #pragma unroll
        for (int kq = 0; kq < 4; kq++) {
            float4 hv = *(const float4*)(h1b + (4 * kk + kq) * 4);
            float hva[4] = {hv.x, hv.y, hv.z, hv.w};
            #pragma unroll
            for (int q = 0; q < 4; q++) {
                acc[0][q] = fmaf(w0a[kq], hva[q], acc[0][q]);
                acc[1][q] = fmaf(w1a[kq], hva[q], acc[1][q]);
                acc[2][q] = fmaf(w2a[kq], hva[q], acc[2][q]);
                acc[3][q] = fmaf(w3a[kq], hva[q], acc[3][q]);
            }
        }
    }

    #pragma unroll
    for (int p = 0; p < 4; p++) {
        float bb = b2[lane + 32 * p];
        #pragma unroll
        for (int q = 0; q < 4; q++) acc[p][q] += bb;
    }

    float scl2[4];
    #pragma unroll
    for (int q = 0; q < 4; q++) {
        float ss = 0.0f;
        #pragma unroll
        for (int p = 0; p < 4; p++) ss = fmaf(acc[p][q], acc[p][q], ss);
        #pragma unroll
        for (int off = 16; off > 0; off >>= 1)
            ss += __shfl_xor_sync(0xffffffffu, ss, off);
        scl2[q] = rsqrtf(ss * (1.0f / HIDDEN) + RMS_EPS);
    }

    float dot[4] = {0.0f, 0.0f, 0.0f, 0.0f};
    #pragma unroll
    for (int p = 0; p < 4; p++) {
        int m = lane + 32 * p;
        float g = sg2[m], w3v = sW3[m];
        #pragma unroll
        for (int q = 0; q < 4; q++) {
            float v = acc[p][q] * scl2[q] * g;
            float h = v * (1.0f / (1.0f + __expf(-v)));
            dot[q] = fmaf(w3v, h, dot[q]);
        }
    }
    #pragma unroll
    for (int q = 0; q < 4; q++) {
        #pragma unroll
        for (int off = 16; off > 0; off >>= 1)
            dot[q] += __shfl_xor_sync(0xffffffffu, dot[q], off);
    }
    if (lane == 0) {
        float bb3 = b3[0];
        #pragma unroll
        for (int q = 0; q < 4; q++) g_table[s0 + q] = dot[q] + bb3;
    }
}

// ---------------------------------------------------------------------------
// Kernel 2: fused kNN + eval, warp-per-query, warps independent. R11 exact
// algorithm (raw sampled tau, two-level radix, (bits,idx)-min boundary).
// Only change: 128-thread blocks (NQ=4), grid 1024 -> higher residency.
// ---------------------------------------------------------------------------
__global__ void __launch_bounds__(128, 12)
knn_eval_kernel(float* __restrict__ out) {
    __shared__ u64 cand[NQ][CAP];          // 10 KB
    __shared__ unsigned hist[NQ][NBUCK];   // 4 KB
    __shared__ int ccnt[NQ];

    const int tid = threadIdx.x;
    const int w = tid >> 5, lane = tid & 31;
    const int i = blockIdx.x * NQ + w;
    const float4 pi = g_pos4[i];
    const unsigned FULL = 0xffffffffu;
    const float INF = __int_as_float(0x7f800000);

    u64* mycand = cand[w];
    unsigned* myhist = hist[w];

    // ---- Phase 1: tau = 8th smallest of the 32 lane-minima ----
    float m = INF;
    #pragma unroll
    for (int s = 0; s < 8; s++) {
        int j = lane * 128 + s * 16;
        float4 q = __ldg(&g_pos4[j]);
        float dx = pi.x - q.x, dy = pi.y - q.y, dz = pi.z - q.z;
        float d = fmaf(dx, dx, fmaf(dy, dy, dz * dz));
        m = fminf(m, d);
    }
    float tau = 0.0f;
    {
        float v = m;
        for (int r = 0; r < 8; r++) {
            float mn = v;
            #pragma unroll
            for (int off = 16; off > 0; off >>= 1)
                mn = fminf(mn, __shfl_xor_sync(FULL, mn, off));
            unsigned own = __ballot_sync(FULL, v == mn);
            if (lane == (__ffs(own) - 1)) v = INF;
            tau = mn;
        }
        if (tau <= 0.0f) tau = 1e-20f;
    }

    // ---- Phase 2: filter with warp-local exact retry ----
    int cnt;
    for (;;) {
        if (lane == 0) ccnt[w] = 0;
        __syncwarp();
        #pragma unroll 4
        for (int it = 0; it < 128; it++) {
            const int j = it * 32 + lane;
            float4 q = __ldg(&g_pos4[j]);
            float dx = pi.x - q.x, dy = pi.y - q.y, dz = pi.z - q.z;
            float d = fmaf(dx, dx, fmaf(dy, dy, dz * dz));
            if (d <= tau) {
                int p = atomicAdd(&ccnt[w], 1);
                if (p < CAP)
                    mycand[p] = ((u64)__float_as_uint(d) << 32) | (unsigned)j;
            }
        }
        __syncwarp();
        cnt = ccnt[w];
        if (cnt >= KSEL && cnt <= CAP) break;
        tau = (cnt < KSEL) ? fmaxf(tau * 4.0f, 1e-20f) : (tau * 0.5f);
    }

    // ---- Phase 3a: coarse radix (bits >> sh) ----
    const unsigned taub = __float_as_uint(tau);
    const int bl = 32 - __clz(taub | 0x10000u);   // bl >= 17 -> sh >= 9
    const int sh = bl - 8;
    const int shf = sh - 8;
    for (int b = lane; b < NBUCK; b += 32) myhist[b] = 0;
    __syncwarp();
    for (int c = lane; c < cnt; c += 32) {
        unsigned bits = (unsigned)(mycand[c] >> 32);
        atomicAdd(&myhist[bits >> sh], 1u);
    }
    __syncwarp();

    int B2, base;
    {
        const int b0 = lane * 8;
        unsigned hv[8];
        unsigned lsum = 0;
        #pragma unroll
        for (int z = 0; z < 8; z++) { hv[z] = myhist[b0 + z]; lsum += hv[z]; }
        unsigned run = lsum;
        #pragma unroll
        for (int off = 1; off < 32; off <<= 1) {
            unsigned v = __shfl_up_sync(FULL, run, off);
            if (lane >= off) run += v;
        }
        run -= lsum;
        u64 pk = 0;
        unsigned r2 = run;
        #pragma unroll
        for (int z = 0; z < 8; z++) {
            if (r2 < KSEL && r2 + hv[z] >= KSEL)
                pk = ((u64)(unsigned)(b0 + z) << 32) | r2;
            r2 += hv[z];
        }
        #pragma unroll
        for (int off = 16; off > 0; off >>= 1) {
            u64 o = __shfl_xor_sync(FULL, pk, off);
            if (o > pk) pk = o;
        }
        B2 = (int)(pk >> 32);
        base = (int)(pk & 0xffffffffu);
    }
    __syncwarp();

    // ---- Phase 3b: fine radix within bucket B2 (next 8 bits) ----
    for (int b = lane; b < NBUCK; b += 32) myhist[b] = 0;
    __syncwarp();
    for (int c = lane; c < cnt; c += 32) {
        unsigned bits = (unsigned)(mycand[c] >> 32);
        if ((int)(bits >> sh) == B2)
            atomicAdd(&myhist[(bits >> shf) & 255u], 1u);
    }
    __syncwarp();

    int B3, base3;
    {
        const int K2 = KSEL - base;
        const int b0 = lane * 8;
        unsigned hv[8];
        unsigned lsum = 0;
        #pragma unroll
        for (int z = 0; z < 8; z++) { hv[z] = myhist[b0 + z]; lsum += hv[z]; }
        unsigned run = lsum;
        #pragma unroll
        for (int off = 1; off < 32; off <<= 1) {
            unsigned v = __shfl_up_sync(FULL, run, off);
            if (lane >= off) run += v;
        }
        run -= lsum;
        u64 pk = 0;
        unsigned r2 = run;
        #pragma unroll
        for (int z = 0; z < 8; z++) {
            if ((int)r2 < K2 && (int)(r2 + hv[z]) >= K2)
                pk = ((u64)(unsigned)(b0 + z) << 32) | r2;
            r2 += hv[z];
        }
        #pragma unroll
        for (int off = 16; off > 0; off >>= 1) {
            u64 o = __shfl_xor_sync(FULL, pk, off);
            if (o > pk) pk = o;
        }
        B3 = (int)(pk >> 32);
        base3 = (int)(pk & 0xffffffffu);
    }
    __syncwarp();

    // ---- Phase 4: accumulate ----
    const float tscale = (float)(TABLE_N - 1);
    float sx = 0.0f, sy = 0.0f, sz = 0.0f;

    #define ACCUM_EDGE(_bits, _j) do {                                     \
        float4 _q = g_pos4[_j];                                            \
        float _dx = pi.x - _q.x, _dy = pi.y - _q.y, _dz = pi.z - _q.z;     \
        float _r = __uint_as_float(_bits);                                 \
        float _u = _r / (1.0f + _r);                                       \
        float _x = _u * tscale;                                            \
        int _i0 = (int)_x; if (_i0 > TABLE_N - 2) _i0 = TABLE_N - 2;       \
        float _f = _x - (float)_i0;                                        \
        float _s0 = g_table[_i0], _s1 = g_table[_i0 + 1];                  \
        float _sv = fmaf(_f, _s1 - _s0, _s0);                              \
        sx = fmaf(_dx, _sv, sx);                                           \
        sy = fmaf(_dy, _sv, sy);                                           \
        sz = fmaf(_dz, _sv, sz);                                           \
    } while (0)

    for (int c = lane; c < cnt; c += 32) {
        u64 key = mycand[c];
        unsigned bits = (unsigned)(key >> 32);
        int cb = (int)(bits >> sh);
        int fb = (int)((bits >> shf) & 255u);
        if (cb < B2 || (cb == B2 && fb < B3))
            ACCUM_EDGE(bits, (int)(key & 0xffffffffu));
    }

    const int need = KSEL - base - base3;
    for (int s = 0; s < need; s++) {
        u64 best = ~0ull;
        for (int c = lane; c < cnt; c += 32) {
            u64 k2 = mycand[c];
            unsigned bits = (unsigned)(k2 >> 32);
            if (k2 != ~0ull && (int)(bits >> sh) == B2 &&
                (int)((bits >> shf) & 255u) == B3)
                best = ullmin2(best, k2);
        }
        #pragma unroll
        for (int off = 16; off > 0; off >>= 1)
            best = ullmin2(best, __shfl_xor_sync(FULL, best, off));
        if (lane == 0) {
            unsigned bb = (unsigned)(best >> 32);
            ACCUM_EDGE(bb, (int)(best & 0xffffffffu));
        }
        for (int c = lane; c < cnt; c += 32)
            if (mycand[c] == best) mycand[c] = ~0ull;
    }
    #undef ACCUM_EDGE

    // ---- Warp reduce + write ----
    #pragma unroll
    for (int off = 16; off > 0; off >>= 1) {
        sx += __shfl_down_sync(FULL, sx, off);
        sy += __shfl_down_sync(FULL, sy, off);
        sz += __shfl_down_sync(FULL, sz, off);
    }
    if (lane == 0) {
        const float invK = 1.0f / (float)KNN;
        out[3 * i]     = pi.x + sx * invK;
        out[3 * i + 1] = pi.y + sy * invK;
        out[3 * i + 2] = pi.z + sz * invK;
    }
}

// ---------------------------------------------------------------------------
// Launch
// ---------------------------------------------------------------------------
extern "C" void kernel_launch(void* const* d_in, const int* in_sizes, int n_in,
                              void* d_out, int out_size) {
    const float* pos = (const float*)d_in[0];
    const float* t   = (const float*)d_in[1];
    const float* W1  = (const float*)d_in[2];
    const float* b1  = (const float*)d_in[3];
    const float* g1  = (const float*)d_in[4];
    const float* W2  = (const float*)d_in[5];
    const float* b2  = (const float*)d_in[6];
    const float* g2  = (const float*)d_in[7];
    const float* W3  = (const float*)d_in[8];
    const float* b3  = (const float*)d_in[9];
    float* out = (float*)d_out;

    const int table_blocks = TABLE_N / 16;            // 128
    const int prep_blocks  = (N_NODE + 127) / 128;    // 32
    table_prep_kernel<<<table_blocks + prep_blocks, 128>>>(
        pos, t, W1, b1, g1, W2, b2, g2, W3, b3);
    knn_eval_kernel<<<N_NODE / NQ, 128>>>(out);
}